// round 16
// baseline (speedup 1.0000x reference)
#include <cuda_runtime.h>
#include <math.h>

// Problem constants (fixed shapes from setup_inputs)
#define D 64
#define R 64
#define T 4096
#define B 8
#define NTOK (B * T)                  // 32768
#define STRENGTH 0.1f
#define SC 0.17677669529663687f       // sqrt(2/64)

#define K1_BLOCKS 256                 // 8 batches * 32 chunks of 128 tokens
#define K1_CHUNKS 32                  // per batch
#define STRIDE2 132                   // interleaved row-pair stride (floats)

// dynamic smem layout (floats)
#define OFF_WP  0                     // [64 pairs][132] interleaved weights
#define OFF_CD  (64 * STRIDE2)        // [64 tok][132] duplicated coords
#define OFF_P   (128 * STRIDE2)       // [16][64] per-token-group partials
#define OFF_B1  (OFF_P + 1024)        // [64]
#define OFF_W2  (OFF_B1 + 64)         // [64]
#define OFF_BR  (OFF_W2 + 64)         // [64]
#define SMEM_FLOATS (OFF_BR + 64)
#define SMEM_BYTES  (SMEM_FLOATS * 4) // 72448 B -> 2 CTAs/SM

typedef unsigned long long ull;

__device__ __forceinline__ ull ffma2(ull a, ull b, ull c) {
    ull d;
    asm("fma.rn.f32x2 %0, %1, %2, %3;" : "=l"(d) : "l"(a), "l"(b), "l"(c));
    return d;
}
__device__ __forceinline__ ull pack2(float v) {
    ull r;
    asm("mov.b64 %0, {%1, %1};" : "=l"(r) : "f"(v));
    return r;
}
__device__ __forceinline__ void unpack2(ull v, float& lo, float& hi) {
    asm("mov.b64 {%0, %1}, %2;" : "=f"(lo), "=f"(hi) : "l"(v));
}

// Scratch (device globals — no allocation)
__device__ float g_phi[(size_t)NTOK * R];        // 8 MB (L2-resident at use)
__device__ float g_partial[K1_BLOCKS * R];
__device__ float g_phisum[B * R];
__device__ unsigned g_done;                      // zero-initialized; self-resets

// ---------------------------------------------------------------------------
// K1: tiled GEMM coords @ [w1^T | W] using dual-fp32 FFMA2.
// 128 tokens/block in two sub-passes; thread tile 4 tokens x 4 row-PAIRS.
// Pair p of thread rg covers rows (rowL, rowL+16), rowL = rg + 32*(p&1),
// in w1 for p<2 and W for p>=2. Weights interleaved; coords duplicated.
// Last-finishing block reduces chunk partials -> g_phisum (deterministic).
// ---------------------------------------------------------------------------
__global__ __launch_bounds__(256) void k1_phi_mass(
    const float* __restrict__ coords, const float* __restrict__ w1,
    const float* __restrict__ b1, const float* __restrict__ w2,
    const float* __restrict__ b2, const float* __restrict__ W,
    const float* __restrict__ bR)
{
    extern __shared__ float sm[];
    float* s_wp   = sm + OFF_WP;
    float* s_cd   = sm + OFF_CD;
    float* s_part = sm + OFF_P;
    float* s_b1   = sm + OFF_B1;
    float* s_w2   = sm + OFF_W2;
    float* s_bR   = sm + OFF_BR;
    __shared__ bool s_last;

    const int tid = threadIdx.x;
    const int bb = blockIdx.x >> 5, chunk = blockIdx.x & 31;
    const int tokBase0 = bb * T + chunk * 128;

    // --- stage weights interleaved: pair q = rg_ + 16*(pl + 2*sect),
    //     lane = m&1 where combined row r = sect*64 + (m*16 + rg_) ---
    for (int idx = tid; idx < 4096; idx += 256) {        // w1[r][k], coalesced read
        const int r = idx >> 6, k = idx & 63;
        const int rg_ = r & 15, m = r >> 4;
        const int q = rg_ + 16 * (m >> 1);
        s_wp[q * STRIDE2 + 2 * k + (m & 1)] = w1[idx];
    }
    for (int idx = tid; idx < 4096; idx += 256) {        // W[k][r], coalesced read
        const int k = idx >> 6, r = idx & 63;
        const int rg_ = r & 15, m = r >> 4;
        const int q = rg_ + 16 * ((m >> 1) + 2);
        s_wp[q * STRIDE2 + 2 * k + (m & 1)] = W[idx];
    }
    if (tid < 64) { s_b1[tid] = b1[tid]; s_w2[tid] = w2[tid]; s_bR[tid] = bR[tid]; }

    const int tg = tid >> 4;       // 0..15 : tokens tg*4 .. tg*4+3
    const int rg = tid & 15;       // 0..15
    const float b2v = __ldg(b2);

    float part[4] = {0.f, 0.f, 0.f, 0.f};

    for (int sub = 0; sub < 2; ++sub) {
        const int tokBase = tokBase0 + sub * 64;

        __syncthreads();
        for (int idx = tid; idx < 4096; idx += 256) {    // coords, duplicated
            const int t = idx >> 6, k = idx & 63;
            const float v = coords[(size_t)(tokBase + t) * D + k];
            *(ull*)(s_cd + t * STRIDE2 + 2 * k) = pack2(v);
        }
        __syncthreads();

        ull acc[4][4];                                   // [token j][pair p]
        #pragma unroll
        for (int j = 0; j < 4; ++j)
            #pragma unroll
            for (int p = 0; p < 4; ++p) acc[j][p] = 0ULL;

        const float* cdb = s_cd + (tg * 4) * STRIDE2;
        const float* wpb = s_wp + rg * STRIDE2;

        #pragma unroll 4
        for (int k2 = 0; k2 < 32; ++k2) {                // 2 k-values per iter
            ulonglong2 w[4], c[4];
            #pragma unroll
            for (int p = 0; p < 4; ++p)
                w[p] = *(const ulonglong2*)(wpb + p * 16 * STRIDE2 + 4 * k2);
            #pragma unroll
            for (int j = 0; j < 4; ++j)
                c[j] = *(const ulonglong2*)(cdb + j * STRIDE2 + 4 * k2);
            #pragma unroll
            for (int j = 0; j < 4; ++j)
                #pragma unroll
                for (int p = 0; p < 4; ++p) {
                    acc[j][p] = ffma2(w[p].x, c[j].x, acc[j][p]);
                    acc[j][p] = ffma2(w[p].y, c[j].y, acc[j][p]);
                }
        }

        // --- epilogue (registers + shfl only) ---
        #pragma unroll
        for (int j = 0; j < 4; ++j) {
            float h0, h1, h2, h3;                        // rows rg,rg+16,rg+32,rg+48
            unpack2(acc[j][0], h0, h1);
            unpack2(acc[j][1], h2, h3);
            float mp = 0.f;
            mp = fmaf(fmaxf(h0 + s_b1[rg],      0.f), s_w2[rg],      mp);
            mp = fmaf(fmaxf(h1 + s_b1[rg + 16], 0.f), s_w2[rg + 16], mp);
            mp = fmaf(fmaxf(h2 + s_b1[rg + 32], 0.f), s_w2[rg + 32], mp);
            mp = fmaf(fmaxf(h3 + s_b1[rg + 48], 0.f), s_w2[rg + 48], mp);
            mp += __shfl_xor_sync(0xffffffffu, mp, 8);
            mp += __shfl_xor_sync(0xffffffffu, mp, 4);
            mp += __shfl_xor_sync(0xffffffffu, mp, 2);
            mp += __shfl_xor_sync(0xffffffffu, mp, 1);
            const float x = mp + b2v;
            const float mass = fmaxf(x, 0.f) + __logf(1.f + __expf(-fabsf(x)));

            float q0, q1, q2, q3;                        // phi rows rg..rg+48
            unpack2(acc[j][2], q0, q1);
            unpack2(acc[j][3], q2, q3);
            const size_t gbase = (size_t)(tokBase + tg * 4 + j) * R;
            const float p0 = SC * __cosf(q0 + s_bR[rg]);
            const float p1 = SC * __cosf(q1 + s_bR[rg + 16]);
            const float p2 = SC * __cosf(q2 + s_bR[rg + 32]);
            const float p3 = SC * __cosf(q3 + s_bR[rg + 48]);
            g_phi[gbase + rg]      = p0;
            g_phi[gbase + rg + 16] = p1;
            g_phi[gbase + rg + 32] = p2;
            g_phi[gbase + rg + 48] = p3;
            part[0] = fmaf(mass, p0, part[0]);
            part[1] = fmaf(mass, p1, part[1]);
            part[2] = fmaf(mass, p2, part[2]);
            part[3] = fmaf(mass, p3, part[3]);
        }
    }

    __syncthreads();
    #pragma unroll
    for (int i = 0; i < 4; ++i)
        s_part[tg * 64 + rg + i * 16] = part[i];
    __syncthreads();

    if (tid < 64) {
        float s = 0.f;
        #pragma unroll
        for (int t = 0; t < 16; ++t) s += s_part[t * 64 + tid];
        g_partial[blockIdx.x * 64 + tid] = s;
    }

    // --- last block reduces partials -> phisum (deterministic fixed order) ---
    __threadfence();
    if (tid == 0)
        s_last = (atomicAdd(&g_done, 1u) == K1_BLOCKS - 1);
    __syncthreads();
    if (s_last) {
        for (int half = 0; half < 2; ++half) {
            const int b = half * 4 + (tid >> 6);
            const int r = tid & 63;
            float s = 0.f;
            #pragma unroll
            for (int c = 0; c < K1_CHUNKS; ++c)
                s += g_partial[(b * K1_CHUNKS + c) * 64 + r];
            g_phisum[b * 64 + r] = s;
        }
        if (tid == 0) g_done = 0;     // reset for next graph replay
    }
}

// ---------------------------------------------------------------------------
// K4: full-line 1 GiB stream of G with fused grav + diagonal add.
// Per-warp grav reduce; no __syncthreads. (Verified at 85.8% DRAM.)
// ---------------------------------------------------------------------------
__global__ __launch_bounds__(256) void k4_copy(const float4* __restrict__ G4,
                                               float4* __restrict__ O4)
{
    const unsigned tile = blockIdx.x;
    const size_t base = (size_t)tile * 1024;
    const unsigned t = threadIdx.x;
    const int lane = (int)(t & 31u);

    float4 v[4];
    #pragma unroll
    for (int k = 0; k < 4; ++k)
        v[k] = __ldcs(G4 + base + k * 256u + t);

    const unsigned bb = tile >> 12;                    // 4096 tiles per batch
    const float* ph = g_phi + (size_t)tile * R;
    const float* ps = g_phisum + bb * 64;
    float x = fmaf(ph[lane], ps[lane], ph[lane + 32] * ps[lane + 32]);
    x += __shfl_xor_sync(0xffffffffu, x, 16);
    x += __shfl_xor_sync(0xffffffffu, x, 8);
    x += __shfl_xor_sync(0xffffffffu, x, 4);
    x += __shfl_xor_sync(0xffffffffu, x, 2);
    x += __shfl_xor_sync(0xffffffffu, x, 1);
    const float gv = STRENGTH * x;                     // warp-uniform

    #pragma unroll
    for (int k = 0; k < 4; ++k) {
        const unsigned within = k * 256u + t;
        const int i  = (int)(within >> 4);
        const int j0 = (int)((within & 15u) << 2);
        const int d  = i - j0;
        if ((unsigned)d < 4u) {
            if      (d == 0) v[k].x += gv;
            else if (d == 1) v[k].y += gv;
            else if (d == 2) v[k].z += gv;
            else             v[k].w += gv;
        }
        __stcs(O4 + base + within, v[k]);
    }
}

// ---------------------------------------------------------------------------
extern "C" void kernel_launch(void* const* d_in, const int* in_sizes, int n_in,
                              void* d_out, int out_size)
{
    const float* G      = (const float*)d_in[0];
    const float* coords = (const float*)d_in[1];
    const float* w1     = (const float*)d_in[2];
    const float* b1     = (const float*)d_in[3];
    const float* w2     = (const float*)d_in[4];
    const float* b2     = (const float*)d_in[5];
    const float* W      = (const float*)d_in[6];
    const float* bR     = (const float*)d_in[7];
    float* out = (float*)d_out;

    cudaFuncSetAttribute(k1_phi_mass,
                         cudaFuncAttributeMaxDynamicSharedMemorySize, SMEM_BYTES);

    k1_phi_mass<<<K1_BLOCKS, 256, SMEM_BYTES>>>(coords, w1, b1, w2, b2, W, bR);
    k4_copy<<<NTOK, 256>>>((const float4*)G, (float4*)out);
}